// round 9
// baseline (speedup 1.0000x reference)
#include <cuda_runtime.h>

// PSRoIAlign: feat [B=4, C=784, H=80, W=80] f32, rois [N=512, 5] f32
// out [N, 16, 7, 7] f32. Channel of output element = r = co*49 + ph*7 + pw.
//
// R7 = R5 thread mapping (one output/thread, 401K threads) + R6 dot8 weight
// vector (no SEL chains) + full load batching: all 4-8 LDG.128 for BOTH sy
// rounds issued before any consume (MLP 8, single latency exposure).

#define PH 7
#define PW 7
#define HH 80
#define WW 80
#define CC 784

__device__ __forceinline__ float dot8(float4 lo, float4 hi, const float* W) {
    float s = lo.x * W[0];
    s = fmaf(lo.y, W[1], s);
    s = fmaf(lo.z, W[2], s);
    s = fmaf(lo.w, W[3], s);
    s = fmaf(hi.x, W[4], s);
    s = fmaf(hi.y, W[5], s);
    s = fmaf(hi.z, W[6], s);
    s = fmaf(hi.w, W[7], s);
    return s;
}

__global__ void __launch_bounds__(256, 4)
psroi_align_kernel(const float* __restrict__ feat,
                   const float* __restrict__ rois,
                   float* __restrict__ out,
                   int total)
{
    int tid = blockIdx.x * blockDim.x + threadIdx.x;
    if (tid >= total) return;

    int n = tid / (PH * PW * 16);
    int r = tid - n * (PH * PW * 16);      // channel index
    int pw = r % PW;
    int ph = (r / PW) % PH;

    const float* roi = rois + n * 5;
    int   b   = (int)roi[0];
    float rx1 = roi[1] * (float)WW;
    float ry1 = roi[2] * (float)HH;
    float rx2 = roi[3] * (float)WW;
    float ry2 = roi[4] * (float)HH;

    float roi_h = fmaxf(ry2 - ry1, 0.1f);
    float roi_w = fmaxf(rx2 - rx1, 0.1f);
    float bin_h = roi_h * (1.0f / PH);
    float bin_w = roi_w * (1.0f / PW);

    const float* __restrict__ f = feat + ((size_t)b * CC + (size_t)r) * (HH * WW);

    // ---- x geometry (shared by both sy rounds) ----
    float xs0 = rx1 + (float)pw * bin_w + 0.25f * bin_w;
    float xs1 = xs0 + 0.5f * bin_w;
    float mx0 = (xs0 >= -1.0f && xs0 <= (float)WW) ? 1.0f : 0.0f;
    float mx1 = (xs1 >= -1.0f && xs1 <= (float)WW) ? 1.0f : 0.0f;
    float xc0 = fminf(fmaxf(xs0, 0.0f), (float)(WW - 1));
    float xc1 = fminf(fmaxf(xs1, 0.0f), (float)(WW - 1));
    int x00 = (int)floorf(xc0);
    int x01 = (int)floorf(xc1);
    int x10 = min(x00 + 1, WW - 1);
    int x11 = min(x01 + 1, WW - 1);
    float lx0 = xc0 - (float)x00, hx0 = 1.0f - lx0;
    float lx1 = xc1 - (float)x01, hx1 = 1.0f - lx1;

    int xa = x00 & ~3;
    int o00 = x00 - xa;                    // 0..3
    int o01 = x10 - xa;                    // 0..4
    int o10 = x01 - xa;                    // 0..5
    int o11 = x11 - xa;                    // 0..6
    bool need_hi = o11 > 3;                // implies xa <= 72, hi window in-bounds

    // ---- 8-wide weight vector (<=4 nonzeros); masks and 1/4 scale folded ----
    float c0 = 0.25f * mx0 * hx0, c1 = 0.25f * mx0 * lx0;
    float c2 = 0.25f * mx1 * hx1, c3 = 0.25f * mx1 * lx1;
    float W[8];
    #pragma unroll
    for (int k = 0; k < 8; ++k) {
        float w = (o00 == k) ? c0 : 0.0f;
        w += (o01 == k) ? c1 : 0.0f;
        w += (o10 == k) ? c2 : 0.0f;
        w += (o11 == k) ? c3 : 0.0f;
        W[k] = w;
    }

    // ---- y geometry for both sy rounds ----
    float ybase = ry1 + (float)ph * bin_h;
    float wA[2], wB[2];
    int offA[2], offB[2];
    #pragma unroll
    for (int sy = 0; sy < 2; ++sy) {
        float ys = ybase + ((float)sy * 0.5f + 0.25f) * bin_h;
        float my = (ys >= -1.0f && ys <= (float)HH) ? 1.0f : 0.0f;
        float yc = fminf(fmaxf(ys, 0.0f), (float)(HH - 1));
        int y0  = (int)floorf(yc);
        int y1i = min(y0 + 1, HH - 1);
        float ly = yc - (float)y0;
        wA[sy] = my * (1.0f - ly);
        wB[sy] = my * ly;
        offA[sy] = y0  * WW + xa;
        offB[sy] = y1i * WW + xa;
    }

    // ---- issue ALL loads before consuming (MLP up to 8) ----
    float4 A0lo = __ldg((const float4*)(f + offA[0]));
    float4 B0lo = __ldg((const float4*)(f + offB[0]));
    float4 A1lo = __ldg((const float4*)(f + offA[1]));
    float4 B1lo = __ldg((const float4*)(f + offB[1]));
    float4 zero = make_float4(0.f, 0.f, 0.f, 0.f);
    float4 A0hi = zero, B0hi = zero, A1hi = zero, B1hi = zero;
    if (need_hi) {
        A0hi = __ldg((const float4*)(f + offA[0] + 4));
        B0hi = __ldg((const float4*)(f + offB[0] + 4));
        A1hi = __ldg((const float4*)(f + offA[1] + 4));
        B1hi = __ldg((const float4*)(f + offB[1] + 4));
    }

    float acc;
    acc  = wA[0] * dot8(A0lo, A0hi, W);
    acc  = fmaf(wB[0], dot8(B0lo, B0hi, W), acc);
    acc  = fmaf(wA[1], dot8(A1lo, A1hi, W), acc);
    acc  = fmaf(wB[1], dot8(B1lo, B1hi, W), acc);

    out[tid] = acc;
}

extern "C" void kernel_launch(void* const* d_in, const int* in_sizes, int n_in,
                              void* d_out, int out_size)
{
    const float* feat = (const float*)d_in[0];
    const float* rois = (const float*)d_in[1];
    float* out = (float*)d_out;

    int N = in_sizes[1] / 5;            // 512 rois
    int total = N * 16 * PH * PW;       // 401408 outputs

    int threads = 256;
    int blocks = (total + threads - 1) / threads;
    psroi_align_kernel<<<blocks, threads>>>(feat, rois, out, total);
}

// round 10
// speedup vs baseline: 1.0420x; 1.0420x over previous
#include <cuda_runtime.h>

// PSRoIAlign: feat [B=4, C=784, H=80, W=80] f32, rois [N=512, 5] f32
// out [N, 16, 7, 7] f32. Channel of output element = r = co*49 + ph*7 + pw.
//
// R10 = R5 structure (one output/thread, sequential sy rounds, <=4 live
// float4) + R6 W-vector consume (dot8, no SEL chains) + forced occupancy:
// __launch_bounds__(256, 6) -> 42 regs, 48 warps/SM. Occupancy has tracked
// duration monotonically across all rounds; this maximizes it while keeping
// the vectorized load pattern.

#define PH 7
#define PW 7
#define HH 80
#define WW 80
#define CC 784

__device__ __forceinline__ float dot8(float4 lo, float4 hi, const float* W) {
    float s = lo.x * W[0];
    s = fmaf(lo.y, W[1], s);
    s = fmaf(lo.z, W[2], s);
    s = fmaf(lo.w, W[3], s);
    s = fmaf(hi.x, W[4], s);
    s = fmaf(hi.y, W[5], s);
    s = fmaf(hi.z, W[6], s);
    s = fmaf(hi.w, W[7], s);
    return s;
}

__global__ void __launch_bounds__(256, 6)
psroi_align_kernel(const float* __restrict__ feat,
                   const float* __restrict__ rois,
                   float* __restrict__ out,
                   int total)
{
    int tid = blockIdx.x * blockDim.x + threadIdx.x;
    if (tid >= total) return;

    int n = tid / (PH * PW * 16);
    int r = tid - n * (PH * PW * 16);      // channel index
    int pw = r % PW;
    int ph = (r / PW) % PH;

    const float* roi = rois + n * 5;
    int   b   = (int)roi[0];
    float rx1 = roi[1] * (float)WW;
    float ry1 = roi[2] * (float)HH;
    float rx2 = roi[3] * (float)WW;
    float ry2 = roi[4] * (float)HH;

    float roi_h = fmaxf(ry2 - ry1, 0.1f);
    float roi_w = fmaxf(rx2 - rx1, 0.1f);
    float bin_h = roi_h * (1.0f / PH);
    float bin_w = roi_w * (1.0f / PW);

    const float* __restrict__ f = feat + ((size_t)b * CC + (size_t)r) * (HH * WW);

    // ---- x geometry (shared by both sy rounds) ----
    float xs0 = rx1 + (float)pw * bin_w + 0.25f * bin_w;
    float xs1 = xs0 + 0.5f * bin_w;
    float mx0 = (xs0 >= -1.0f && xs0 <= (float)WW) ? 1.0f : 0.0f;
    float mx1 = (xs1 >= -1.0f && xs1 <= (float)WW) ? 1.0f : 0.0f;
    float xc0 = fminf(fmaxf(xs0, 0.0f), (float)(WW - 1));
    float xc1 = fminf(fmaxf(xs1, 0.0f), (float)(WW - 1));
    int x00 = (int)floorf(xc0);
    int x01 = (int)floorf(xc1);
    int x10 = min(x00 + 1, WW - 1);
    int x11 = min(x01 + 1, WW - 1);
    float lx0 = xc0 - (float)x00, hx0 = 1.0f - lx0;
    float lx1 = xc1 - (float)x01, hx1 = 1.0f - lx1;

    int xa = x00 & ~3;
    int o00 = x00 - xa;                    // 0..3
    int o01 = x10 - xa;                    // 0..4
    int o10 = x01 - xa;                    // 0..5
    int o11 = x11 - xa;                    // 0..6
    bool need_hi = o11 > 3;                // implies xa <= 72, hi window in-bounds

    // ---- 8-wide weight vector (<=4 nonzeros); masks and 1/4 scale folded.
    // o00..o11 are dead after this block (register-friendly).
    float c0 = 0.25f * mx0 * hx0, c1 = 0.25f * mx0 * lx0;
    float c2 = 0.25f * mx1 * hx1, c3 = 0.25f * mx1 * lx1;
    float W[8];
    #pragma unroll
    for (int k = 0; k < 8; ++k) {
        float w = (o00 == k) ? c0 : 0.0f;
        w += (o01 == k) ? c1 : 0.0f;
        w += (o10 == k) ? c2 : 0.0f;
        w += (o11 == k) ? c3 : 0.0f;
        W[k] = w;
    }

    float ybase = ry1 + (float)ph * bin_h;
    float acc = 0.0f;

    // ---- sequential sy rounds: at most 4 float4 live at a time ----
    #pragma unroll
    for (int sy = 0; sy < 2; ++sy) {
        float ys = ybase + ((float)sy * 0.5f + 0.25f) * bin_h;
        float my = (ys >= -1.0f && ys <= (float)HH) ? 1.0f : 0.0f;
        float yc = fminf(fmaxf(ys, 0.0f), (float)(HH - 1));
        int y0  = (int)floorf(yc);
        int y1i = min(y0 + 1, HH - 1);
        float ly = yc - (float)y0;
        float hy = 1.0f - ly;

        const float* rowA = f + y0  * WW + xa;
        const float* rowB = f + y1i * WW + xa;

        float4 Alo = __ldg((const float4*)rowA);
        float4 Blo = __ldg((const float4*)rowB);
        float4 Ahi = make_float4(0.f, 0.f, 0.f, 0.f);
        float4 Bhi = Ahi;
        if (need_hi) {
            Ahi = __ldg((const float4*)(rowA + 4));
            Bhi = __ldg((const float4*)(rowB + 4));
        }

        acc = fmaf(my * hy, dot8(Alo, Ahi, W), acc);
        acc = fmaf(my * ly, dot8(Blo, Bhi, W), acc);
    }

    out[tid] = acc;
}

extern "C" void kernel_launch(void* const* d_in, const int* in_sizes, int n_in,
                              void* d_out, int out_size)
{
    const float* feat = (const float*)d_in[0];
    const float* rois = (const float*)d_in[1];
    float* out = (float*)d_out;

    int N = in_sizes[1] / 5;            // 512 rois
    int total = N * 16 * PH * PW;       // 401408 outputs

    int threads = 256;
    int blocks = (total + threads - 1) / threads;
    psroi_align_kernel<<<blocks, threads>>>(feat, rois, out, total);
}